// round 1
// baseline (speedup 1.0000x reference)
#include <cuda_runtime.h>

// Problem constants
#define BB   8
#define SS   1024
#define NXX  1024
#define HH   16
#define DHH  64
#define NVV  49
#define NTT  14
#define NSS  1087          // 14 + 49 + 1024
#define PREF 63            // tags + visual prefix length

// Scratch (device globals: allocation-free per harness rules)
__device__ float g_q[(size_t)BB * HH * SS * DHH];   // Q in [B,H,S,dh], 32 MB
__device__ float g_a[(size_t)BB * SS * NXX];        // merged-head attn out, 32 MB

// ---------------------------------------------------------------------------
// Generic SGEMM  C[M,N] = A[M,K] @ W[K,N] + bias, with mode-specific scatter.
// BM=BN=128, BK=8, 256 threads, 8x8 microtile per thread.
// MODE 0: QKV   (A=x,    N=3072) -> Q to g_q, K/V scattered into present(text)
// MODE 1: VIS   (A=vis,  N=2048) -> K/V into present at pos 14+p
// MODE 2: TAGS  (A=tags, N=2048) -> K/V into present at pos p
// MODE 3: PROJ  (A=g_a,  N=1024) -> plain write into out (a section)
// Requirements met by all calls: K % 8 == 0, N % 128 == 0 (only M is ragged).
// ---------------------------------------------------------------------------
template <int MODE>
__global__ __launch_bounds__(256) void gemm_kernel(
    const float* __restrict__ A, const float* __restrict__ W,
    const float* __restrict__ bias, float* __restrict__ present,
    float* __restrict__ outp, int M, int N, int K)
{
    __shared__ float As[8][128];   // transposed A tile
    __shared__ float Bs[8][128];

    const float* Ap = (MODE == 3) ? g_a : A;

    const int bm = blockIdx.y, bn = blockIdx.x;
    const int tid = threadIdx.x;
    const int ty = tid >> 4, tx = tid & 15;

    // global-load assignments
    const int arow = tid >> 1;            // 0..127
    const int acol = (tid & 1) << 2;      // 0 or 4
    const int wrow = tid >> 5;            // 0..7
    const int wcol = (tid & 31) << 2;     // 0..124

    const int gArow = bm * 128 + arow;
    const float* aptr = Ap + (size_t)gArow * K + acol;
    const float* wptr = W + (size_t)wrow * N + bn * 128 + wcol;

    float acc[8][8];
#pragma unroll
    for (int i = 0; i < 8; i++)
#pragma unroll
        for (int j = 0; j < 8; j++) acc[i][j] = 0.f;

    for (int k0 = 0; k0 < K; k0 += 8) {
        float4 av = make_float4(0.f, 0.f, 0.f, 0.f);
        if (gArow < M) av = *(const float4*)(aptr + k0);
        As[acol + 0][arow] = av.x;
        As[acol + 1][arow] = av.y;
        As[acol + 2][arow] = av.z;
        As[acol + 3][arow] = av.w;
        *(float4*)&Bs[wrow][wcol] = *(const float4*)(wptr + (size_t)k0 * N);
        __syncthreads();
#pragma unroll
        for (int kk = 0; kk < 8; kk++) {
            float4 a0 = *(const float4*)&As[kk][ty * 8];
            float4 a1 = *(const float4*)&As[kk][ty * 8 + 4];
            float4 b0 = *(const float4*)&Bs[kk][tx * 8];
            float4 b1 = *(const float4*)&Bs[kk][tx * 8 + 4];
            float ar[8] = {a0.x, a0.y, a0.z, a0.w, a1.x, a1.y, a1.z, a1.w};
            float br[8] = {b0.x, b0.y, b0.z, b0.w, b1.x, b1.y, b1.z, b1.w};
#pragma unroll
            for (int i = 0; i < 8; i++)
#pragma unroll
                for (int j = 0; j < 8; j++) acc[i][j] += ar[i] * br[j];
        }
        __syncthreads();
    }

    // epilogue scatter
#pragma unroll
    for (int i = 0; i < 8; i++) {
        int r = bm * 128 + ty * 8 + i;
        if (r >= M) continue;
#pragma unroll
        for (int j = 0; j < 8; j++) {
            int c = bn * 128 + tx * 8 + j;
            float val = acc[i][j] + bias[c];
            if (MODE == 0) {
                int b = r >> 10, s = r & 1023;
                int sect = c >> 10, cc = c & 1023;
                int h = cc >> 6, d = cc & 63;
                if (sect == 0)
                    g_q[((((size_t)b * HH + h) * SS + s) << 6) + d] = val;
                else
                    present[(((((size_t)b * 2 + (sect - 1)) * HH + h) * NSS +
                              (PREF + s)) << 6) + d] = val;
            } else if (MODE == 1) {
                int b = r / NVV, p = r % NVV;
                int sect = c >> 10, cc = c & 1023;
                int h = cc >> 6, d = cc & 63;
                present[(((((size_t)b * 2 + sect) * HH + h) * NSS +
                          (NTT + p)) << 6) + d] = val;
            } else if (MODE == 2) {
                int b = r / NTT, p = r % NTT;
                int sect = c >> 10, cc = c & 1023;
                int h = cc >> 6, d = cc & 63;
                present[(((((size_t)b * 2 + sect) * HH + h) * NSS + p) << 6) + d] = val;
            } else {
                outp[(size_t)r * NXX + c] = val;
            }
        }
    }
}

// ---------------------------------------------------------------------------
// Flash-attention: 64-query tile per block, 64-key tiles, online softmax.
// Thread grid 16x16; thread owns q-rows ty*4..+3 and key/d cols {tx+16u}.
// Causal mask: key j visible to query i iff j <= i + 63 (prefix fully visible).
// Static shared = 3 * 64*64 floats = 48 KB exactly. K tile XOR-swizzled.
// ---------------------------------------------------------------------------
__global__ __launch_bounds__(256) void attn_kernel(const float* __restrict__ present)
{
    __shared__ float Qs[64 * 64];
    __shared__ float KVs[64 * 64];
    __shared__ float Ps[64 * 64];

    const int qt = blockIdx.x, h = blockIdx.y, b = blockIdx.z;
    const int tid = threadIdx.x;
    const int ty = tid >> 4, tx = tid & 15;

    // Load Q tile
    const float* qbase = g_q + ((((size_t)b * HH + h) * SS + qt * 64) << 6);
#pragma unroll
    for (int i = 0; i < 4; i++) {
        int f = tid + 256 * i;
        int row = f >> 4, c4 = (f & 15) << 2;
        *(float4*)&Qs[row * 64 + c4] = *(const float4*)(qbase + row * 64 + c4);
    }

    const float* kbase = present + (((((size_t)b * 2 + 0) * HH + h) * NSS) << 6);
    const float* vbase = present + (((((size_t)b * 2 + 1) * HH + h) * NSS) << 6);

    float m[4], l[4], O[4][4];
#pragma unroll
    for (int i = 0; i < 4; i++) {
        m[i] = -1e30f; l[i] = 0.f;
#pragma unroll
        for (int u = 0; u < 4; u++) O[i][u] = 0.f;
    }

    const int iglob0 = qt * 64 + ty * 4;
    const int tmax = min(qt + 1, 16);

    for (int t = 0; t <= tmax; t++) {
        __syncthreads();   // prior iteration done reading KVs / Ps (also orders Qs)
        // Load K tile (XOR-swizzled quads: quad' = quad ^ (row & 15))
#pragma unroll
        for (int i = 0; i < 4; i++) {
            int f = tid + 256 * i;
            int row = f >> 4, q4 = f & 15;
            int pos = t * 64 + row;
            float4 kv4 = make_float4(0.f, 0.f, 0.f, 0.f);
            if (pos < NSS) kv4 = *(const float4*)(kbase + ((size_t)pos << 6) + (q4 << 2));
            *(float4*)&KVs[row * 64 + ((q4 ^ (row & 15)) << 2)] = kv4;
        }
        __syncthreads();

        // S = Q K^T  (thread: 4 q-rows x key cols {tx+16u})
        float Sv[4][4];
#pragma unroll
        for (int i = 0; i < 4; i++)
#pragma unroll
            for (int u = 0; u < 4; u++) Sv[i][u] = 0.f;

#pragma unroll
        for (int k = 0; k < 64; k += 4) {
            float4 qv[4], kf[4];
#pragma unroll
            for (int i = 0; i < 4; i++)
                qv[i] = *(const float4*)&Qs[(ty * 4 + i) * 64 + k];
#pragma unroll
            for (int u = 0; u < 4; u++) {
                int row = tx + 16 * u;   // row & 15 == tx
                kf[u] = *(const float4*)&KVs[row * 64 + (((k >> 2) ^ tx) << 2)];
            }
#pragma unroll
            for (int i = 0; i < 4; i++)
#pragma unroll
                for (int u = 0; u < 4; u++)
                    Sv[i][u] += qv[i].x * kf[u].x + qv[i].y * kf[u].y +
                                qv[i].z * kf[u].z + qv[i].w * kf[u].w;
        }

        // scale + mask + online softmax
#pragma unroll
        for (int i = 0; i < 4; i++) {
            int ig = iglob0 + i;
            float rmax = -1e30f;
#pragma unroll
            for (int u = 0; u < 4; u++) {
                int jg = t * 64 + tx + 16 * u;
                float s = Sv[i][u] * 0.125f;
                if (jg > ig + PREF || jg >= NSS) s = -1e30f;
                Sv[i][u] = s;
                rmax = fmaxf(rmax, s);
            }
#pragma unroll
            for (int off = 8; off >= 1; off >>= 1)
                rmax = fmaxf(rmax, __shfl_xor_sync(0xffffffffu, rmax, off));
            float mn = fmaxf(m[i], rmax);
            float corr = __expf(m[i] - mn);
            float rsum = 0.f;
#pragma unroll
            for (int u = 0; u < 4; u++) {
                float e = __expf(Sv[i][u] - mn);
                Sv[i][u] = e;
                rsum += e;
            }
#pragma unroll
            for (int off = 8; off >= 1; off >>= 1)
                rsum += __shfl_xor_sync(0xffffffffu, rsum, off);
            l[i] = l[i] * corr + rsum;
            m[i] = mn;
#pragma unroll
            for (int u = 0; u < 4; u++) O[i][u] *= corr;
#pragma unroll
            for (int u = 0; u < 4; u++)
                Ps[(ty * 4 + i) * 64 + tx + 16 * u] = Sv[i][u];
        }
        __syncthreads();   // K reads done, P written

        // Load V tile (plain layout; reads are conflict-free)
#pragma unroll
        for (int i = 0; i < 4; i++) {
            int f = tid + 256 * i;
            int row = f >> 4, c4 = (f & 15) << 2;
            int pos = t * 64 + row;
            float4 vv = make_float4(0.f, 0.f, 0.f, 0.f);
            if (pos < NSS) vv = *(const float4*)(vbase + ((size_t)pos << 6) + c4);
            *(float4*)&KVs[row * 64 + c4] = vv;
        }
        __syncthreads();

        // O += P @ V
#pragma unroll
        for (int j = 0; j < 64; j += 4) {
            float4 pv[4];
#pragma unroll
            for (int i = 0; i < 4; i++)
                pv[i] = *(const float4*)&Ps[(ty * 4 + i) * 64 + j];
            float pr[4][4];
#pragma unroll
            for (int i = 0; i < 4; i++) {
                pr[i][0] = pv[i].x; pr[i][1] = pv[i].y;
                pr[i][2] = pv[i].z; pr[i][3] = pv[i].w;
            }
#pragma unroll
            for (int jj = 0; jj < 4; jj++) {
                float vr[4];
#pragma unroll
                for (int u = 0; u < 4; u++)
                    vr[u] = KVs[(j + jj) * 64 + tx + 16 * u];
#pragma unroll
                for (int i = 0; i < 4; i++)
#pragma unroll
                    for (int u = 0; u < 4; u++)
                        O[i][u] += pr[i][jj] * vr[u];
            }
        }
    }

    // finalize + write merged-head layout a[b, s, h*64 + d]
    float* abase = g_a + ((size_t)b * SS + qt * 64) * NXX + h * 64;
#pragma unroll
    for (int i = 0; i < 4; i++) {
        float inv = 1.f / l[i];
#pragma unroll
        for (int u = 0; u < 4; u++)
            abase[(ty * 4 + i) * NXX + tx + 16 * u] = O[i][u] * inv;
    }
}

// ---------------------------------------------------------------------------
extern "C" void kernel_launch(void* const* d_in, const int* in_sizes, int n_in,
                              void* d_out, int out_size)
{
    const float* x      = (const float*)d_in[0];
    const float* vis    = (const float*)d_in[1];
    const float* tags   = (const float*)d_in[2];
    const float* W_attn = (const float*)d_in[3];
    const float* b_attn = (const float*)d_in[4];
    const float* W_vis  = (const float*)d_in[5];
    const float* b_vis  = (const float*)d_in[6];
    const float* W_tags = (const float*)d_in[7];
    const float* b_tags = (const float*)d_in[8];
    const float* W_proj = (const float*)d_in[9];
    const float* b_proj = (const float*)d_in[10];

    float* out = (float*)d_out;
    float* present = out + (size_t)BB * SS * NXX;   // a first, then present

    // QKV: [8192,1024] @ [1024,3072]
    gemm_kernel<0><<<dim3(3072 / 128, 8192 / 128), 256>>>(
        x, W_attn, b_attn, present, nullptr, BB * SS, 3 * NXX, NXX);
    // visual: [392,1024] @ [1024,2048]
    gemm_kernel<1><<<dim3(2048 / 128, (BB * NVV + 127) / 128), 256>>>(
        vis, W_vis, b_vis, present, nullptr, BB * NVV, 2 * NXX, 1024);
    // tags: [112,400] @ [400,2048]
    gemm_kernel<2><<<dim3(2048 / 128, 1), 256>>>(
        tags, W_tags, b_tags, present, nullptr, BB * NTT, 2 * NXX, 400);
    // attention
    attn_kernel<<<dim3(SS / 64, HH, BB), 256>>>(present);
    // proj: [8192,1024] @ [1024,1024] -> a section of out
    gemm_kernel<3><<<dim3(1024 / 128, 8192 / 128), 256>>>(
        nullptr, W_proj, b_proj, nullptr, out, BB * SS, NXX, NXX);
}

// round 2
// speedup vs baseline: 1.9657x; 1.9657x over previous
#include <cuda_runtime.h>
#include <cstdint>

// Problem constants
#define BB   8
#define SS   1024
#define NXX  1024
#define HH   16
#define DHH  64
#define NVV  49
#define NTT  14
#define NSS  1087          // 14 + 49 + 1024
#define PREF 63            // tags + visual prefix length

// Scratch (device globals: allocation-free per harness rules)
__device__ float g_q[(size_t)BB * HH * SS * DHH];   // Q in [B,H,S,dh], 32 MB
__device__ float g_a[(size_t)BB * SS * NXX];        // merged-head attn out, 32 MB

__device__ __forceinline__ uint32_t f2tf32(float x) {
    uint32_t y;
    asm("cvt.rna.tf32.f32 %0, %1;" : "=r"(y) : "f"(x));
    return y;
}

__device__ __forceinline__ void mma_tf32(float* c, const uint32_t* a, const uint32_t* b) {
    asm volatile(
        "mma.sync.aligned.m16n8k8.row.col.f32.tf32.tf32.f32 "
        "{%0,%1,%2,%3}, {%4,%5,%6,%7}, {%8,%9}, {%0,%1,%2,%3};\n"
        : "+f"(c[0]), "+f"(c[1]), "+f"(c[2]), "+f"(c[3])
        : "r"(a[0]), "r"(a[1]), "r"(a[2]), "r"(a[3]), "r"(b[0]), "r"(b[1]));
}

// scatter helper shared by GEMM epilogues
template <int MODE>
__device__ __forceinline__ void scatter(int r, int c, float val,
                                        float* __restrict__ present,
                                        float* __restrict__ outp)
{
    if (MODE == 0) {
        int b = r >> 10, s = r & 1023;
        int sect = c >> 10, cc = c & 1023;
        int h = cc >> 6, d = cc & 63;
        if (sect == 0)
            g_q[((((size_t)b * HH + h) * SS + s) << 6) + d] = val;
        else
            present[(((((size_t)b * 2 + (sect - 1)) * HH + h) * NSS +
                      (PREF + s)) << 6) + d] = val;
    } else if (MODE == 1) {
        int b = r / NVV, p = r % NVV;
        int sect = c >> 10, cc = c & 1023;
        int h = cc >> 6, d = cc & 63;
        present[(((((size_t)b * 2 + sect) * HH + h) * NSS + (NTT + p)) << 6) + d] = val;
    } else if (MODE == 2) {
        int b = r / NTT, p = r % NTT;
        int sect = c >> 10, cc = c & 1023;
        int h = cc >> 6, d = cc & 63;
        present[(((((size_t)b * 2 + sect) * HH + h) * NSS + p) << 6) + d] = val;
    } else {
        outp[(size_t)r * NXX + c] = val;
    }
}

// ---------------------------------------------------------------------------
// tf32 tensor-core GEMM: C[M,N] = A[M,K] @ W[K,N] + bias, mode scatter.
// BM=BN=128, BK=32, 256 threads (4x2 warps, 32x64 per warp).
// Requires K % 32 == 0, N % 128 == 0. M may be ragged.
// MODE 0: QKV (A=x) / MODE 1: VIS / MODE 3: PROJ (A=g_a)
// ---------------------------------------------------------------------------
template <int MODE>
__global__ __launch_bounds__(256) void mma_gemm(
    const float* __restrict__ A, const float* __restrict__ W,
    const float* __restrict__ bias, float* __restrict__ present,
    float* __restrict__ outp, int M, int N, int K)
{
    __shared__ uint32_t As[128 * 36];   // row stride 36 floats (conflict-free frags)
    __shared__ uint32_t Bs[32 * 136];   // row stride 136 floats

    const float* Ap = (MODE == 3) ? g_a : A;

    const int bm = blockIdx.y, bn = blockIdx.x;
    const int tid = threadIdx.x;
    const int warp = tid >> 5, lane = tid & 31;
    const int wm = warp >> 1, wn = warp & 1;
    const int lq = lane >> 2, lr = lane & 3;   // groupID, threadID_in_group

    float acc[2][8][4];
#pragma unroll
    for (int mt = 0; mt < 2; mt++)
#pragma unroll
        for (int nt = 0; nt < 8; nt++)
#pragma unroll
            for (int u = 0; u < 4; u++) acc[mt][nt][u] = 0.f;

    float4 ra[4], rb[4];
    const float4 z4 = make_float4(0.f, 0.f, 0.f, 0.f);

    // prologue load (kt = 0)
#pragma unroll
    for (int i = 0; i < 4; i++) {
        int flat = tid + 256 * i;
        {   // A: 128 rows x 8 float4
            int row = flat >> 3, c4 = flat & 7;
            int gr = bm * 128 + row;
            ra[i] = (gr < M) ? *(const float4*)(Ap + (size_t)gr * K + c4 * 4) : z4;
        }
        {   // B: 32 rows x 32 float4
            int row = flat >> 5, c4 = flat & 31;
            rb[i] = *(const float4*)(W + (size_t)row * N + bn * 128 + c4 * 4);
        }
    }

    for (int kt = 0; kt < K; kt += 32) {
        __syncthreads();
        // store staged tile (convert to tf32)
#pragma unroll
        for (int i = 0; i < 4; i++) {
            int flat = tid + 256 * i;
            {
                int row = flat >> 3, c4 = flat & 7;
                uint4 p;
                p.x = f2tf32(ra[i].x); p.y = f2tf32(ra[i].y);
                p.z = f2tf32(ra[i].z); p.w = f2tf32(ra[i].w);
                *(uint4*)&As[row * 36 + c4 * 4] = p;
            }
            {
                int row = flat >> 5, c4 = flat & 31;
                uint4 p;
                p.x = f2tf32(rb[i].x); p.y = f2tf32(rb[i].y);
                p.z = f2tf32(rb[i].z); p.w = f2tf32(rb[i].w);
                *(uint4*)&Bs[row * 136 + c4 * 4] = p;
            }
        }
        __syncthreads();

        // prefetch next tile into registers (overlaps with compute)
        if (kt + 32 < K) {
#pragma unroll
            for (int i = 0; i < 4; i++) {
                int flat = tid + 256 * i;
                {
                    int row = flat >> 3, c4 = flat & 7;
                    int gr = bm * 128 + row;
                    ra[i] = (gr < M) ? *(const float4*)(Ap + (size_t)gr * K + kt + 32 + c4 * 4) : z4;
                }
                {
                    int row = flat >> 5, c4 = flat & 31;
                    rb[i] = *(const float4*)(W + (size_t)(kt + 32 + row) * N + bn * 128 + c4 * 4);
                }
            }
        }

        // compute on current tile
#pragma unroll
        for (int g = 0; g < 4; g++) {
            uint32_t af[2][4];
#pragma unroll
            for (int mt = 0; mt < 2; mt++) {
                int r = wm * 32 + mt * 16 + lq;
                af[mt][0] = As[r * 36 + g * 8 + lr];
                af[mt][1] = As[(r + 8) * 36 + g * 8 + lr];
                af[mt][2] = As[r * 36 + g * 8 + lr + 4];
                af[mt][3] = As[(r + 8) * 36 + g * 8 + lr + 4];
            }
            uint32_t bf[8][2];
#pragma unroll
            for (int nt = 0; nt < 8; nt++) {
                int n = wn * 64 + nt * 8 + lq;
                bf[nt][0] = Bs[(g * 8 + lr) * 136 + n];
                bf[nt][1] = Bs[(g * 8 + lr + 4) * 136 + n];
            }
#pragma unroll
            for (int mt = 0; mt < 2; mt++)
#pragma unroll
                for (int nt = 0; nt < 8; nt++)
                    mma_tf32(acc[mt][nt], af[mt], bf[nt]);
        }
    }

    // epilogue: bias + scatter
#pragma unroll
    for (int mt = 0; mt < 2; mt++) {
        int r0 = bm * 128 + wm * 32 + mt * 16 + lq;
#pragma unroll
        for (int nt = 0; nt < 8; nt++) {
            int c0 = bn * 128 + wn * 64 + nt * 8 + (lr << 1);
            float bz0 = bias[c0], bz1 = bias[c0 + 1];
            if (r0 < M) {
                scatter<MODE>(r0, c0,     acc[mt][nt][0] + bz0, present, outp);
                scatter<MODE>(r0, c0 + 1, acc[mt][nt][1] + bz1, present, outp);
            }
            if (r0 + 8 < M) {
                scatter<MODE>(r0 + 8, c0,     acc[mt][nt][2] + bz0, present, outp);
                scatter<MODE>(r0 + 8, c0 + 1, acc[mt][nt][3] + bz1, present, outp);
            }
        }
    }
}

// ---------------------------------------------------------------------------
// Legacy FFMA SGEMM kept for tags (K=400 not %32). MODE 2 only.
// ---------------------------------------------------------------------------
template <int MODE>
__global__ __launch_bounds__(256) void gemm_kernel(
    const float* __restrict__ A, const float* __restrict__ W,
    const float* __restrict__ bias, float* __restrict__ present,
    float* __restrict__ outp, int M, int N, int K)
{
    __shared__ float As[8][128];
    __shared__ float Bs[8][128];

    const int bm = blockIdx.y, bn = blockIdx.x;
    const int tid = threadIdx.x;
    const int ty = tid >> 4, tx = tid & 15;

    const int arow = tid >> 1;
    const int acol = (tid & 1) << 2;
    const int wrow = tid >> 5;
    const int wcol = (tid & 31) << 2;

    const int gArow = bm * 128 + arow;
    const float* aptr = A + (size_t)gArow * K + acol;
    const float* wptr = W + (size_t)wrow * N + bn * 128 + wcol;

    float acc[8][8];
#pragma unroll
    for (int i = 0; i < 8; i++)
#pragma unroll
        for (int j = 0; j < 8; j++) acc[i][j] = 0.f;

    for (int k0 = 0; k0 < K; k0 += 8) {
        float4 av = make_float4(0.f, 0.f, 0.f, 0.f);
        if (gArow < M) av = *(const float4*)(aptr + k0);
        As[acol + 0][arow] = av.x;
        As[acol + 1][arow] = av.y;
        As[acol + 2][arow] = av.z;
        As[acol + 3][arow] = av.w;
        *(float4*)&Bs[wrow][wcol] = *(const float4*)(wptr + (size_t)k0 * N);
        __syncthreads();
#pragma unroll
        for (int kk = 0; kk < 8; kk++) {
            float4 a0 = *(const float4*)&As[kk][ty * 8];
            float4 a1 = *(const float4*)&As[kk][ty * 8 + 4];
            float4 b0 = *(const float4*)&Bs[kk][tx * 8];
            float4 b1 = *(const float4*)&Bs[kk][tx * 8 + 4];
            float ar[8] = {a0.x, a0.y, a0.z, a0.w, a1.x, a1.y, a1.z, a1.w};
            float br[8] = {b0.x, b0.y, b0.z, b0.w, b1.x, b1.y, b1.z, b1.w};
#pragma unroll
            for (int i = 0; i < 8; i++)
#pragma unroll
                for (int j = 0; j < 8; j++) acc[i][j] += ar[i] * br[j];
        }
        __syncthreads();
    }

#pragma unroll
    for (int i = 0; i < 8; i++) {
        int r = bm * 128 + ty * 8 + i;
        if (r >= M) continue;
#pragma unroll
        for (int j = 0; j < 8; j++) {
            int c = bn * 128 + tx * 8 + j;
            scatter<MODE>(r, c, acc[i][j] + bias[c], present, outp);
        }
    }
}

// ---------------------------------------------------------------------------
// Flash-attention: 64-query tile per block, 64-key tiles, online softmax.
// ---------------------------------------------------------------------------
__global__ __launch_bounds__(256) void attn_kernel(const float* __restrict__ present)
{
    __shared__ float Qs[64 * 64];
    __shared__ float KVs[64 * 64];
    __shared__ float Ps[64 * 64];

    const int qt = blockIdx.x, h = blockIdx.y, b = blockIdx.z;
    const int tid = threadIdx.x;
    const int ty = tid >> 4, tx = tid & 15;

    const float* qbase = g_q + ((((size_t)b * HH + h) * SS + qt * 64) << 6);
#pragma unroll
    for (int i = 0; i < 4; i++) {
        int f = tid + 256 * i;
        int row = f >> 4, c4 = (f & 15) << 2;
        *(float4*)&Qs[row * 64 + c4] = *(const float4*)(qbase + row * 64 + c4);
    }

    const float* kbase = present + (((((size_t)b * 2 + 0) * HH + h) * NSS) << 6);
    const float* vbase = present + (((((size_t)b * 2 + 1) * HH + h) * NSS) << 6);

    float m[4], l[4], O[4][4];
#pragma unroll
    for (int i = 0; i < 4; i++) {
        m[i] = -1e30f; l[i] = 0.f;
#pragma unroll
        for (int u = 0; u < 4; u++) O[i][u] = 0.f;
    }

    const int iglob0 = qt * 64 + ty * 4;
    const int tmax = min(qt + 1, 16);

    for (int t = 0; t <= tmax; t++) {
        __syncthreads();
#pragma unroll
        for (int i = 0; i < 4; i++) {
            int f = tid + 256 * i;
            int row = f >> 4, q4 = f & 15;
            int pos = t * 64 + row;
            float4 kv4 = make_float4(0.f, 0.f, 0.f, 0.f);
            if (pos < NSS) kv4 = *(const float4*)(kbase + ((size_t)pos << 6) + (q4 << 2));
            *(float4*)&KVs[row * 64 + ((q4 ^ (row & 15)) << 2)] = kv4;
        }
        __syncthreads();

        float Sv[4][4];
#pragma unroll
        for (int i = 0; i < 4; i++)
#pragma unroll
            for (int u = 0; u < 4; u++) Sv[i][u] = 0.f;

#pragma unroll
        for (int k = 0; k < 64; k += 4) {
            float4 qv[4], kf[4];
#pragma unroll
            for (int i = 0; i < 4; i++)
                qv[i] = *(const float4*)&Qs[(ty * 4 + i) * 64 + k];
#pragma unroll
            for (int u = 0; u < 4; u++) {
                int row = tx + 16 * u;
                kf[u] = *(const float4*)&KVs[row * 64 + (((k >> 2) ^ tx) << 2)];
            }
#pragma unroll
            for (int i = 0; i < 4; i++)
#pragma unroll
                for (int u = 0; u < 4; u++)
                    Sv[i][u] += qv[i].x * kf[u].x + qv[i].y * kf[u].y +
                                qv[i].z * kf[u].z + qv[i].w * kf[u].w;
        }

#pragma unroll
        for (int i = 0; i < 4; i++) {
            int ig = iglob0 + i;
            float rmax = -1e30f;
#pragma unroll
            for (int u = 0; u < 4; u++) {
                int jg = t * 64 + tx + 16 * u;
                float s = Sv[i][u] * 0.125f;
                if (jg > ig + PREF || jg >= NSS) s = -1e30f;
                Sv[i][u] = s;
                rmax = fmaxf(rmax, s);
            }
#pragma unroll
            for (int off = 8; off >= 1; off >>= 1)
                rmax = fmaxf(rmax, __shfl_xor_sync(0xffffffffu, rmax, off));
            float mn = fmaxf(m[i], rmax);
            float corr = __expf(m[i] - mn);
            float rsum = 0.f;
#pragma unroll
            for (int u = 0; u < 4; u++) {
                float e = __expf(Sv[i][u] - mn);
                Sv[i][u] = e;
                rsum += e;
            }
#pragma unroll
            for (int off = 8; off >= 1; off >>= 1)
                rsum += __shfl_xor_sync(0xffffffffu, rsum, off);
            l[i] = l[i] * corr + rsum;
            m[i] = mn;
#pragma unroll
            for (int u = 0; u < 4; u++) O[i][u] *= corr;
#pragma unroll
            for (int u = 0; u < 4; u++)
                Ps[(ty * 4 + i) * 64 + tx + 16 * u] = Sv[i][u];
        }
        __syncthreads();

#pragma unroll
        for (int i = 0; i < 4; i++) {
            int f = tid + 256 * i;
            int row = f >> 4, c4 = (f & 15) << 2;
            int pos = t * 64 + row;
            float4 vv = make_float4(0.f, 0.f, 0.f, 0.f);
            if (pos < NSS) vv = *(const float4*)(vbase + ((size_t)pos << 6) + c4);
            *(float4*)&KVs[row * 64 + c4] = vv;
        }
        __syncthreads();

#pragma unroll
        for (int j = 0; j < 64; j += 4) {
            float4 pv[4];
#pragma unroll
            for (int i = 0; i < 4; i++)
                pv[i] = *(const float4*)&Ps[(ty * 4 + i) * 64 + j];
            float pr[4][4];
#pragma unroll
            for (int i = 0; i < 4; i++) {
                pr[i][0] = pv[i].x; pr[i][1] = pv[i].y;
                pr[i][2] = pv[i].z; pr[i][3] = pv[i].w;
            }
#pragma unroll
            for (int jj = 0; jj < 4; jj++) {
                float vr[4];
#pragma unroll
                for (int u = 0; u < 4; u++)
                    vr[u] = KVs[(j + jj) * 64 + tx + 16 * u];
#pragma unroll
                for (int i = 0; i < 4; i++)
#pragma unroll
                    for (int u = 0; u < 4; u++)
                        O[i][u] += pr[i][jj] * vr[u];
            }
        }
    }

    float* abase = g_a + ((size_t)b * SS + qt * 64) * NXX + h * 64;
#pragma unroll
    for (int i = 0; i < 4; i++) {
        float inv = 1.f / l[i];
#pragma unroll
        for (int u = 0; u < 4; u++)
            abase[(ty * 4 + i) * NXX + tx + 16 * u] = O[i][u] * inv;
    }
}

// ---------------------------------------------------------------------------
extern "C" void kernel_launch(void* const* d_in, const int* in_sizes, int n_in,
                              void* d_out, int out_size)
{
    const float* x      = (const float*)d_in[0];
    const float* vis    = (const float*)d_in[1];
    const float* tags   = (const float*)d_in[2];
    const float* W_attn = (const float*)d_in[3];
    const float* b_attn = (const float*)d_in[4];
    const float* W_vis  = (const float*)d_in[5];
    const float* b_vis  = (const float*)d_in[6];
    const float* W_tags = (const float*)d_in[7];
    const float* b_tags = (const float*)d_in[8];
    const float* W_proj = (const float*)d_in[9];
    const float* b_proj = (const float*)d_in[10];

    float* out = (float*)d_out;
    float* present = out + (size_t)BB * SS * NXX;   // a first, then present

    // QKV: [8192,1024] @ [1024,3072]  (tf32 tensor cores)
    mma_gemm<0><<<dim3(3072 / 128, 8192 / 128), 256>>>(
        x, W_attn, b_attn, present, nullptr, BB * SS, 3 * NXX, NXX);
    // visual: [392,1024] @ [1024,2048]  (tf32)
    mma_gemm<1><<<dim3(2048 / 128, (BB * NVV + 127) / 128), 256>>>(
        vis, W_vis, b_vis, present, nullptr, BB * NVV, 2 * NXX, 1024);
    // tags: [112,400] @ [400,2048]  (FFMA, K not %32)
    gemm_kernel<2><<<dim3(2048 / 128, 1), 256>>>(
        tags, W_tags, b_tags, present, nullptr, BB * NTT, 2 * NXX, 400);
    // attention
    attn_kernel<<<dim3(SS / 64, HH, BB), 256>>>(present);
    // proj: [8192,1024] @ [1024,1024]  (tf32)
    mma_gemm<3><<<dim3(1024 / 128, 8192 / 128), 256>>>(
        nullptr, W_proj, b_proj, nullptr, out, BB * SS, NXX, NXX);
}